// round 14
// baseline (speedup 1.0000x reference)
#include <cuda_runtime.h>
#include <cstdint>

// ---------------- problem constants ----------------
// B=256, D0=16, D1=32, D2=64, D_FFN=2048, F1=2048, F2=1024
// out dtype float32, out_size = 256*16*32*64 = 8388608

#define BM 128
#define BN 256
#define BK 32
#define BKP 36          // padded smem row stride (floats) -> conflict-free frags
#define STAGES 3
#define NTHREADS 256
#define STAGE_F ((BM + BN) * BKP)   // floats per stage

// scratch: h1 [B, D0, 2048] (32MB), h2 [B, D1, 2048] (64MB)
__device__ __align__(128) float g_h1[256L * 16 * 2048];
__device__ __align__(128) float g_h2[256L * 32 * 2048];

static __device__ __forceinline__ uint32_t smem_u32(const void* p) {
    return (uint32_t)__cvta_generic_to_shared(p);
}
static __device__ __forceinline__ void cp_async16(uint32_t s, const void* g) {
    asm volatile("cp.async.cg.shared.global [%0], [%1], 16;\n" :: "r"(s), "l"(g));
}
static __device__ __forceinline__ void cp_commit() {
    asm volatile("cp.async.commit_group;\n" ::: "memory");
}
template <int N_>
static __device__ __forceinline__ void cp_wait() {
    asm volatile("cp.async.wait_group %0;\n" :: "n"(N_) : "memory");
}
// NOTE: no cvt — HMMA.tf32 reads bits[31:13]; raw fp32 bits act as RZ tf32.
static __device__ __forceinline__ void mma_tf32(float c[4],
                                                uint32_t a0, uint32_t a1, uint32_t a2, uint32_t a3,
                                                uint32_t b0, uint32_t b1) {
    asm volatile(
        "mma.sync.aligned.m16n8k8.row.col.f32.tf32.tf32.f32 "
        "{%0,%1,%2,%3}, {%4,%5,%6,%7}, {%8,%9}, {%0,%1,%2,%3};\n"
        : "+f"(c[0]), "+f"(c[1]), "+f"(c[2]), "+f"(c[3])
        : "r"(a0), "r"(a1), "r"(a2), "r"(a3), "r"(b0), "r"(b1));
}

// Grouped TN GEMM:  C[m,n] = sum_k A_g[m,k] * W_g[n,k]
// A elem (m,k) at A0 + g*a_g + m*a_ldr + (k>>6)*a_ldblk + (k&63)   (handles the
// mlp2 transpose-gather without a transpose pass)
// W elem (n,k) at W0 + g*w_g + n*K + k
// out elem     at out0 + g*o_g + m*o_ldr + (n>>6)*o_ldblk + (n&63)
// MODE 0: out = gelu(acc + bias[n]);  MODE 1: out = aux0[same idx] + 0.5*(acc+bias[n])
template <int MODE>
__global__ void __launch_bounds__(NTHREADS)
grouped_gemm(const float* __restrict__ A0, long a_g, long a_ldr, long a_ldblk,
             const float* __restrict__ W0, long w_g,
             const float* __restrict__ bias0,
             float* __restrict__ out0, long o_g, long o_ldr, long o_ldblk,
             const float* __restrict__ aux0,
             int N, int K) {
    extern __shared__ float smem[];

    const int g  = blockIdx.z;
    const int bm = blockIdx.y;
    const int bn = blockIdx.x;

    const float* A    = A0 + (long)g * a_g;
    const float* W    = W0 + (long)g * w_g;
    const float* bias = bias0 + (long)g * (long)N;

    const int tid  = threadIdx.x;
    const int warp = tid >> 5;
    const int lane = tid & 31;
    const int wm   = (warp >> 2) * 64;    // warp m offset (0 / 64)          [2 rows]
    const int wn   = (warp & 3) * 64;     // warp n offset (0/64/128/192)    [4 cols]
    const int qrow = lane >> 2;           // 0..7
    const int qk   = lane & 3;            // 0..3

    // 64x64 warp tile: 4 (M) x 8 (N) mma grid -> 128 accumulator regs
    float c[4][8][4];
#pragma unroll
    for (int mi = 0; mi < 4; mi++)
#pragma unroll
        for (int ni = 0; ni < 8; ni++)
#pragma unroll
            for (int r = 0; r < 4; r++) c[mi][ni][r] = 0.0f;

    // Per-stage loader: (BM+BN)*BK floats = 3072 x 16B chunks, 12 per thread.
    auto load_tile = [&](int kt, int s) {
        float* as = smem + (long)s * STAGE_F;
        float* bs = as + BM * BKP;
        const int kbase = kt * BK;
#pragma unroll
        for (int i = 0; i < 12; i++) {
            const int id = tid + NTHREADS * i;
            const int kq = (id & 7) * 4;
            const int kg = kbase + kq;
            if (i < 4) {                                   // A rows 0..127
                const int row = id >> 3;
                cp_async16(smem_u32(&as[row * BKP + kq]),
                           A + (long)(bm * BM + row) * a_ldr
                             + (long)(kg >> 6) * a_ldblk + (kg & 63));
            } else {                                       // B rows 0..255
                const int row = (id - 1024) >> 3;
                cp_async16(smem_u32(&bs[row * BKP + kq]),
                           W + (long)(bn * BN + row) * K + kg);
            }
        }
    };

    const int KT = K / BK;

    // prologue: prefetch STAGES-1 tiles
#pragma unroll
    for (int s = 0; s < STAGES - 1; s++) {
        load_tile(s, s);
        cp_commit();
    }

    for (int kt = 0; kt < KT; kt++) {
        cp_wait<STAGES - 2>();
        __syncthreads();   // tile kt visible; also protects stage about to be reloaded

        const int nt = kt + STAGES - 1;
        if (nt < KT) load_tile(nt, nt % STAGES);
        cp_commit();

        const uint32_t* as = (const uint32_t*)(smem + (long)(kt % STAGES) * STAGE_F);
        const uint32_t* bs = as + BM * BKP;

#pragma unroll
        for (int ks = 0; ks < BK / 8; ks++) {
            const int k0 = ks * 8 + qk;
            uint32_t af[4][4], bf[8][2];
#pragma unroll
            for (int mi = 0; mi < 4; mi++) {
                const int m = wm + mi * 16 + qrow;
                af[mi][0] = as[m * BKP + k0];
                af[mi][1] = as[(m + 8) * BKP + k0];
                af[mi][2] = as[m * BKP + k0 + 4];
                af[mi][3] = as[(m + 8) * BKP + k0 + 4];
            }
#pragma unroll
            for (int ni = 0; ni < 8; ni++) {
                const int n = wn + ni * 8 + qrow;
                bf[ni][0] = bs[n * BKP + k0];
                bf[ni][1] = bs[n * BKP + k0 + 4];
            }
#pragma unroll
            for (int mi = 0; mi < 4; mi++)
#pragma unroll
                for (int ni = 0; ni < 8; ni++)
                    mma_tf32(c[mi][ni], af[mi][0], af[mi][1], af[mi][2], af[mi][3],
                             bf[ni][0], bf[ni][1]);
        }
    }
    cp_wait<0>();

    // -------- epilogue --------
    const long og = (long)g * o_g;
#pragma unroll
    for (int mi = 0; mi < 4; mi++) {
        const int mrow = bm * BM + wm + mi * 16 + qrow;
#pragma unroll
        for (int ni = 0; ni < 8; ni++) {
            const int ncol = bn * BN + wn + ni * 8 + qk * 2;
#pragma unroll
            for (int rr = 0; rr < 2; rr++) {
                const long mterm = og + (long)(mrow + rr * 8) * o_ldr;
#pragma unroll
                for (int cc = 0; cc < 2; cc++) {
                    const int n_g = ncol + cc;
                    const float v = c[mi][ni][rr * 2 + cc] + __ldg(bias + n_g);
                    const long oaddr = mterm + (long)(n_g >> 6) * o_ldblk + (n_g & 63);
                    if (MODE == 0) {
                        out0[oaddr] = 0.5f * v * (1.0f + erff(v * 0.70710678118654752f));
                    } else {
                        out0[oaddr] = aux0[oaddr] + 0.5f * v;
                    }
                }
            }
        }
    }
}

extern "C" void kernel_launch(void* const* d_in, const int* in_sizes, int n_in,
                              void* d_out, int out_size) {
    const float* x    = (const float*)d_in[0];
    const float* W0_1 = (const float*)d_in[1];
    const float* b0_1 = (const float*)d_in[2];
    const float* W1_1 = (const float*)d_in[3];
    const float* b1_1 = (const float*)d_in[4];
    const float* W0_2 = (const float*)d_in[5];
    const float* b0_2 = (const float*)d_in[6];
    const float* W1_2 = (const float*)d_in[7];
    const float* b1_2 = (const float*)d_in[8];
    float* out = (float*)d_out;

    void* p1 = nullptr; void* p2 = nullptr;
    cudaGetSymbolAddress(&p1, g_h1);
    cudaGetSymbolAddress(&p2, g_h2);
    float* h1 = (float*)p1;
    float* h2 = (float*)p2;

    const size_t shm = (size_t)STAGES * STAGE_F * sizeof(float);  // 165888
    cudaFuncSetAttribute(grouped_gemm<0>, cudaFuncAttributeMaxDynamicSharedMemorySize, (int)shm);
    cudaFuncSetAttribute(grouped_gemm<1>, cudaFuncAttributeMaxDynamicSharedMemorySize, (int)shm);

    dim3 blk(NTHREADS);

    // G1a: h1 = gelu(x1 @ W0_1^T + b0_1)   M=256, N=2048, K=2048, G=16
    grouped_gemm<0><<<dim3(2048 / BN, 256 / BM, 16), blk, shm>>>(
        x, 2048L, 32768L, 64L,
        W0_1, 2048L * 2048L,
        b0_1,
        h1, 2048L, 32768L, 64L,
        nullptr, 2048, 2048);

    // G2a: h2 = gelu(x2 @ W0_2^T + b0_2)   M=256, N=2048, K=1024, G=32
    // A gather: x2[b, i*64+d] = x[b,i,j,d] -> base x + j*64, ldr 32768, ldblk 2048
    grouped_gemm<0><<<dim3(2048 / BN, 256 / BM, 32), blk, shm>>>(
        x, 64L, 32768L, 2048L,
        W0_2, 2048L * 1024L,
        b0_2,
        h2, 2048L, 65536L, 64L,
        nullptr, 2048, 1024);

    // G1b: out = x + 0.5*(h1 @ W1_1^T + b1_1)   N=2048, K=2048, G=16
    grouped_gemm<1><<<dim3(2048 / BN, 256 / BM, 16), blk, shm>>>(
        h1, 2048L, 32768L, 64L,
        W1_1, 2048L * 2048L,
        b1_1,
        out, 2048L, 32768L, 64L,
        x, 2048, 2048);

    // G2b: out += 0.5*(h2 @ W1_2^T + b1_2)   N=1024, K=2048, G=32
    // out scatter: n=(i,d) -> base out + j*64, ldr 32768, ldblk 2048; aux = out (RMW)
    grouped_gemm<1><<<dim3(1024 / BN, 256 / BM, 32), blk, shm>>>(
        h2, 2048L, 65536L, 64L,
        W1_2, 1024L * 2048L,
        b1_2,
        out, 64L, 32768L, 2048L,
        out, 1024, 2048);

    (void)in_sizes; (void)n_in; (void)out_size;
}

// round 15
// speedup vs baseline: 1.1350x; 1.1350x over previous
#include <cuda_runtime.h>
#include <cstdint>

// ---------------- problem constants ----------------
// B=256, D0=16, D1=32, D2=64, D_FFN=2048, F1=2048, F2=1024
// out dtype float32, out_size = 256*16*32*64 = 8388608

#define BM 128
#define BN 128
#define BK 32
#define BKP 36          // padded smem row stride (floats): rows at 144B -> LDSM conflict-free
#define STAGES 3
#define NTHREADS 256
#define STAGE_F ((BM + BN) * BKP)

// scratch: h1 [B, D0, 2048] (32MB), h2 [B, D1, 2048] (64MB)
__device__ __align__(128) float g_h1[256L * 16 * 2048];
__device__ __align__(128) float g_h2[256L * 32 * 2048];

static __device__ __forceinline__ uint32_t smem_u32(const void* p) {
    return (uint32_t)__cvta_generic_to_shared(p);
}
static __device__ __forceinline__ void cp_async16(uint32_t s, const void* g) {
    asm volatile("cp.async.cg.shared.global [%0], [%1], 16;\n" :: "r"(s), "l"(g));
}
static __device__ __forceinline__ void cp_commit() {
    asm volatile("cp.async.commit_group;\n" ::: "memory");
}
template <int N_>
static __device__ __forceinline__ void cp_wait() {
    asm volatile("cp.async.wait_group %0;\n" :: "n"(N_) : "memory");
}
// ldmatrix: 4x (8 rows x 16B) matrices; lane l gets (row l/4, 4B-col l%4) of each.
// For tf32 m16n8k8 this is EXACTLY the A fragment (a0..a3) / B fragment layout
// when smem rows are [m][k] or [n][k] with 16B k-chunks.
static __device__ __forceinline__ void ldsm_x4(uint32_t& r0, uint32_t& r1,
                                               uint32_t& r2, uint32_t& r3, uint32_t addr) {
    asm volatile("ldmatrix.sync.aligned.m8n8.x4.shared.b16 {%0,%1,%2,%3}, [%4];"
                 : "=r"(r0), "=r"(r1), "=r"(r2), "=r"(r3) : "r"(addr));
}
// NOTE: no cvt — HMMA.tf32 reads bits[31:13]; raw fp32 bits act as RZ tf32.
static __device__ __forceinline__ void mma_tf32(float c[4],
                                                uint32_t a0, uint32_t a1, uint32_t a2, uint32_t a3,
                                                uint32_t b0, uint32_t b1) {
    asm volatile(
        "mma.sync.aligned.m16n8k8.row.col.f32.tf32.tf32.f32 "
        "{%0,%1,%2,%3}, {%4,%5,%6,%7}, {%8,%9}, {%0,%1,%2,%3};\n"
        : "+f"(c[0]), "+f"(c[1]), "+f"(c[2]), "+f"(c[3])
        : "r"(a0), "r"(a1), "r"(a2), "r"(a3), "r"(b0), "r"(b1));
}

// Grouped TN GEMM:  C[m,n] = sum_k A_g[m,k] * W_g[n,k]
// A elem (m,k) at A0 + g*a_g + m*a_ldr + (k>>6)*a_ldblk + (k&63)  (mlp2 transpose-gather)
// W elem (n,k) at W0 + g*w_g + n*K + k
// out elem     at out0 + g*o_g + m*o_ldr + (n>>6)*o_ldblk + (n&63)
// MODE 0: out = gelu(acc + bias[n]);  MODE 1: out = aux0[same idx] + 0.5*(acc+bias[n])
template <int MODE>
__global__ void __launch_bounds__(NTHREADS, 2)
grouped_gemm(const float* __restrict__ A0, long a_g, long a_ldr, long a_ldblk,
             const float* __restrict__ W0, long w_g,
             const float* __restrict__ bias0,
             float* __restrict__ out0, long o_g, long o_ldr, long o_ldblk,
             const float* __restrict__ aux0,
             int N, int K) {
    extern __shared__ float smem[];

    const int g  = blockIdx.z;
    const int bm = blockIdx.y;
    const int bn = blockIdx.x;

    const float* A    = A0 + (long)g * a_g;
    const float* W    = W0 + (long)g * w_g;
    const float* bias = bias0 + (long)g * (long)N;

    const int tid  = threadIdx.x;
    const int lrow = tid >> 3;            // loader row (0..31)
    const int lk4  = (tid & 7) * 4;       // loader k offset

    const int warp = tid >> 5;
    const int lane = tid & 31;
    const int wm   = (warp >> 2) * 64;    // warp m offset (0 / 64)
    const int wn   = (warp & 3) * 32;     // warp n offset (0/32/64/96)
    const int qrow = lane >> 2;           // 0..7
    const int qk   = lane & 3;            // 0..3

    // ldmatrix per-lane source rows/cols (float units within as/bs)
    // A x4: m0 rows(l0-7)@k0 | m1 rows+8(l8-15)@k0 | m2 rows@k0+4 | m3 rows+8@k0+4
    const int arow  = ((lane >> 3) & 1) * 8 + (lane & 7);
    const int akoff = (lane >> 4) * 4;
    // B x4 (n-pair p): n rows(l0-7)@k0 | n rows(l8-15)@k0+4 | n+8(l16-23)@k0 | n+8(l24-31)@k0+4
    const int brow  = (lane >> 4) * 8 + (lane & 7);
    const int bkoff = ((lane >> 3) & 1) * 4;

    float c[4][4][4];
#pragma unroll
    for (int mi = 0; mi < 4; mi++)
#pragma unroll
        for (int ni = 0; ni < 4; ni++)
#pragma unroll
            for (int r = 0; r < 4; r++) c[mi][ni][r] = 0.0f;

    auto load_tile = [&](int kt, int s) {
        float* as = smem + (long)s * STAGE_F;
        float* bs = as + BM * BKP;
        const long kg   = (long)kt * BK + lk4;
        const long ablk = (kg >> 6) * a_ldblk + (kg & 63);
#pragma unroll
        for (int p = 0; p < 4; p++) {
            const int r = lrow + p * 32;
            cp_async16(smem_u32(&as[r * BKP + lk4]),
                       A + (long)(bm * BM + r) * a_ldr + ablk);
        }
#pragma unroll
        for (int p = 0; p < 4; p++) {
            const int r = lrow + p * 32;
            cp_async16(smem_u32(&bs[r * BKP + lk4]),
                       W + (long)(bn * BN + r) * K + kg);
        }
    };

    const int KT = K / BK;

#pragma unroll
    for (int s = 0; s < STAGES - 1; s++) {
        load_tile(s, s);
        cp_commit();
    }

    for (int kt = 0; kt < KT; kt++) {
        cp_wait<STAGES - 2>();
        __syncthreads();   // tile kt visible; also protects stage about to be reloaded

        const int nt = kt + STAGES - 1;
        if (nt < KT) load_tile(nt, nt % STAGES);
        cp_commit();

        const uint32_t as_u = smem_u32(smem + (long)(kt % STAGES) * STAGE_F);
        const uint32_t bs_u = as_u + BM * BKP * 4;
        const uint32_t a_base = as_u + (uint32_t)(((wm + arow) * BKP + akoff) * 4);
        const uint32_t b_base = bs_u + (uint32_t)(((wn + brow) * BKP + bkoff) * 4);

#pragma unroll
        for (int ks = 0; ks < BK / 8; ks++) {
            uint32_t af[4][4], bf[2][4];
#pragma unroll
            for (int mi = 0; mi < 4; mi++)
                ldsm_x4(af[mi][0], af[mi][1], af[mi][2], af[mi][3],
                        a_base + (uint32_t)((mi * 16 * BKP + ks * 8) * 4));
#pragma unroll
            for (int p = 0; p < 2; p++)
                // r0=b0(ni=2p) r1=b1(2p) r2=b0(2p+1) r3=b1(2p+1)
                ldsm_x4(bf[p][0], bf[p][1], bf[p][2], bf[p][3],
                        b_base + (uint32_t)((p * 16 * BKP + ks * 8) * 4));
#pragma unroll
            for (int mi = 0; mi < 4; mi++)
#pragma unroll
                for (int ni = 0; ni < 4; ni++) {
                    const int p = ni >> 1, h = (ni & 1) * 2;
                    mma_tf32(c[mi][ni], af[mi][0], af[mi][1], af[mi][2], af[mi][3],
                             bf[p][h], bf[p][h + 1]);
                }
        }
    }
    cp_wait<0>();

    // -------- epilogue --------
    const long og = (long)g * o_g;
#pragma unroll
    for (int mi = 0; mi < 4; mi++) {
        const int mrow = bm * BM + wm + mi * 16 + qrow;
#pragma unroll
        for (int ni = 0; ni < 4; ni++) {
            const int ncol = bn * BN + wn + ni * 8 + qk * 2;
#pragma unroll
            for (int rr = 0; rr < 2; rr++) {
                const long mterm = og + (long)(mrow + rr * 8) * o_ldr;
#pragma unroll
                for (int cc = 0; cc < 2; cc++) {
                    const int n_g = ncol + cc;
                    const float v = c[mi][ni][rr * 2 + cc] + __ldg(bias + n_g);
                    const long oaddr = mterm + (long)(n_g >> 6) * o_ldblk + (n_g & 63);
                    if (MODE == 0) {
                        out0[oaddr] = 0.5f * v * (1.0f + erff(v * 0.70710678118654752f));
                    } else {
                        out0[oaddr] = aux0[oaddr] + 0.5f * v;
                    }
                }
            }
        }
    }
}

extern "C" void kernel_launch(void* const* d_in, const int* in_sizes, int n_in,
                              void* d_out, int out_size) {
    const float* x    = (const float*)d_in[0];
    const float* W0_1 = (const float*)d_in[1];
    const float* b0_1 = (const float*)d_in[2];
    const float* W1_1 = (const float*)d_in[3];
    const float* b1_1 = (const float*)d_in[4];
    const float* W0_2 = (const float*)d_in[5];
    const float* b0_2 = (const float*)d_in[6];
    const float* W1_2 = (const float*)d_in[7];
    const float* b1_2 = (const float*)d_in[8];
    float* out = (float*)d_out;

    void* p1 = nullptr; void* p2 = nullptr;
    cudaGetSymbolAddress(&p1, g_h1);
    cudaGetSymbolAddress(&p2, g_h2);
    float* h1 = (float*)p1;
    float* h2 = (float*)p2;

    const size_t shm = (size_t)STAGES * STAGE_F * sizeof(float);  // 110592
    cudaFuncSetAttribute(grouped_gemm<0>, cudaFuncAttributeMaxDynamicSharedMemorySize, (int)shm);
    cudaFuncSetAttribute(grouped_gemm<1>, cudaFuncAttributeMaxDynamicSharedMemorySize, (int)shm);

    dim3 blk(NTHREADS);

    // G1a: h1 = gelu(x1 @ W0_1^T + b0_1)   M=256, N=2048, K=2048, G=16
    grouped_gemm<0><<<dim3(2048 / BN, 256 / BM, 16), blk, shm>>>(
        x, 2048L, 32768L, 64L,
        W0_1, 2048L * 2048L,
        b0_1,
        h1, 2048L, 32768L, 64L,
        nullptr, 2048, 2048);

    // G2a: h2 = gelu(x2 @ W0_2^T + b0_2)   M=256, N=2048, K=1024, G=32
    // A gather: x2[b, i*64+d] = x[b,i,j,d] -> base x + j*64, ldr 32768, ldblk 2048
    grouped_gemm<0><<<dim3(2048 / BN, 256 / BM, 32), blk, shm>>>(
        x, 64L, 32768L, 2048L,
        W0_2, 2048L * 1024L,
        b0_2,
        h2, 2048L, 65536L, 64L,
        nullptr, 2048, 1024);

    // G1b: out = x + 0.5*(h1 @ W1_1^T + b1_1)   N=2048, K=2048, G=16
    grouped_gemm<1><<<dim3(2048 / BN, 256 / BM, 16), blk, shm>>>(
        h1, 2048L, 32768L, 64L,
        W1_1, 2048L * 2048L,
        b1_1,
        out, 2048L, 32768L, 64L,
        x, 2048, 2048);

    // G2b: out += 0.5*(h2 @ W1_2^T + b1_2)   N=1024, K=2048, G=32
    // out scatter: n=(i,d) -> base out + j*64, ldr 32768, ldblk 2048; aux = out (RMW)
    grouped_gemm<1><<<dim3(1024 / BN, 256 / BM, 32), blk, shm>>>(
        h2, 2048L, 65536L, 64L,
        W1_2, 1024L * 2048L,
        b1_2,
        out, 64L, 32768L, 2048L,
        out, 1024, 2048);

    (void)in_sizes; (void)n_in; (void)out_size;
}

// round 16
// speedup vs baseline: 1.2740x; 1.1225x over previous
#include <cuda_runtime.h>
#include <cstdint>

// ---------------- problem constants ----------------
// B=256, D0=16, D1=32, D2=64, D_FFN=2048, F1=2048, F2=1024
// out dtype float32, out_size = 256*16*32*64 = 8388608

#define BM 64
#define BN 128
#define BK 32
#define STAGES 3
#define NTHREADS 256
#define STAGE_F ((BM + BN) * BK)     // 6144 floats = 24 KB

// scratch: h1 [B, D0, 2048] (32MB), h2 [B, D1, 2048] (64MB)
__device__ __align__(128) float g_h1[256L * 16 * 2048];
__device__ __align__(128) float g_h2[256L * 32 * 2048];

static __device__ __forceinline__ uint32_t smem_u32(const void* p) {
    return (uint32_t)__cvta_generic_to_shared(p);
}
static __device__ __forceinline__ void cp_async16(uint32_t s, const void* g) {
    asm volatile("cp.async.cg.shared.global [%0], [%1], 16;\n" :: "r"(s), "l"(g));
}
static __device__ __forceinline__ void cp_commit() {
    asm volatile("cp.async.commit_group;\n" ::: "memory");
}
template <int N_>
static __device__ __forceinline__ void cp_wait() {
    asm volatile("cp.async.wait_group %0;\n" :: "n"(N_) : "memory");
}
// ldmatrix x4: four 8-row x 16B matrices; smem rows XOR-swizzled (chunk ^= row&7)
static __device__ __forceinline__ void ldsm_x4(uint32_t& r0, uint32_t& r1,
                                               uint32_t& r2, uint32_t& r3, uint32_t addr) {
    asm volatile("ldmatrix.sync.aligned.m8n8.x4.shared.b16 {%0,%1,%2,%3}, [%4];"
                 : "=r"(r0), "=r"(r1), "=r"(r2), "=r"(r3) : "r"(addr));
}
// NOTE: no cvt — HMMA.tf32 reads bits[31:13]; raw fp32 bits act as RZ tf32.
static __device__ __forceinline__ void mma_tf32(float c[4],
                                                uint32_t a0, uint32_t a1, uint32_t a2, uint32_t a3,
                                                uint32_t b0, uint32_t b1) {
    asm volatile(
        "mma.sync.aligned.m16n8k8.row.col.f32.tf32.tf32.f32 "
        "{%0,%1,%2,%3}, {%4,%5,%6,%7}, {%8,%9}, {%0,%1,%2,%3};\n"
        : "+f"(c[0]), "+f"(c[1]), "+f"(c[2]), "+f"(c[3])
        : "r"(a0), "r"(a1), "r"(a2), "r"(a3), "r"(b0), "r"(b1));
}

// Grouped TN GEMM:  C[m,n] = sum_k A_g[m,k] * W_g[n,k]
// A elem (m,k) at A0 + g*a_g + m*a_ldr + (k>>6)*a_ldblk + (k&63)  (mlp2 transpose-gather)
// W elem (n,k) at W0 + g*w_g + n*K + k
// out elem     at out0 + g*o_g + m*o_ldr + (n>>6)*o_ldblk + (n&63)
// MODE 0: out = gelu(acc + bias[n]);  MODE 1: out = aux0[same idx] + 0.5*(acc+bias[n])
template <int MODE>
__global__ void __launch_bounds__(NTHREADS, 3)
grouped_gemm(const float* __restrict__ A0, long a_g, long a_ldr, long a_ldblk,
             const float* __restrict__ W0, long w_g,
             const float* __restrict__ bias0,
             float* __restrict__ out0, long o_g, long o_ldr, long o_ldblk,
             const float* __restrict__ aux0,
             int N, int K) {
    extern __shared__ float smem[];

    const int g  = blockIdx.z;
    const int bm = blockIdx.y;
    const int bn = blockIdx.x;

    const float* A    = A0 + (long)g * a_g;
    const float* W    = W0 + (long)g * w_g;
    const float* bias = bias0 + (long)g * (long)N;

    const int tid  = threadIdx.x;
    const int warp = tid >> 5;
    const int lane = tid & 31;
    const int wm   = (warp >> 2) * 32;    // warp m offset (0 / 32)
    const int wn   = (warp & 3) * 32;     // warp n offset (0/32/64/96)
    const int qrow = lane >> 2;           // 0..7
    const int qk   = lane & 3;            // 0..3

    // ldmatrix lane geometry (chunk = 16B unit along k)
    const int arow  = ((lane >> 3) & 1) * 8 + (lane & 7);  // A: m0 r0-7@k0|m1 r8-15@k0|m2 r0-7@k0+4|m3 r8-15@k0+4
    const int achk  = lane >> 4;                           // 0,0,1,1 per 8-lane group
    const int brow  = (lane >> 4) * 8 + (lane & 7);        // B: r0-7@k0 | r0-7@k0+4 | r8-15@k0 | r8-15@k0+4
    const int bchk  = (lane >> 3) & 1;
    const int lxor  = lane & 7;                            // swizzle term (row&7 == lane&7 here)

    // 32x32 warp tile: 2 (M) x 4 (N) mma grid -> 32 accumulator regs
    float c[2][4][4];
#pragma unroll
    for (int mi = 0; mi < 2; mi++)
#pragma unroll
        for (int ni = 0; ni < 4; ni++)
#pragma unroll
            for (int r = 0; r < 4; r++) c[mi][ni][r] = 0.0f;

    // Loader: A 64x32 (512 chunks, 2/thread), B 128x32 (1024 chunks, 4/thread).
    // Chunk c of row r stored at float offset row*32 + (c ^ (r&7))*4.
    auto load_tile = [&](int kt, int s) {
        float* as = smem + (long)s * STAGE_F;
        float* bs = as + BM * BK;
        const int kbase = kt * BK;
#pragma unroll
        for (int i = 0; i < 2; i++) {
            const int id  = tid + NTHREADS * i;
            const int row = id >> 3;
            const int ch  = id & 7;
            const int kg  = kbase + ch * 4;
            cp_async16(smem_u32(&as[row * BK + ((ch ^ (row & 7)) << 2)]),
                       A + (long)(bm * BM + row) * a_ldr
                         + (long)(kg >> 6) * a_ldblk + (kg & 63));
        }
#pragma unroll
        for (int i = 0; i < 4; i++) {
            const int id  = tid + NTHREADS * i;
            const int row = id >> 3;
            const int ch  = id & 7;
            const int kg  = kbase + ch * 4;
            cp_async16(smem_u32(&bs[row * BK + ((ch ^ (row & 7)) << 2)]),
                       W + (long)(bn * BN + row) * K + kg);
        }
    };

    const int KT = K / BK;

#pragma unroll
    for (int s = 0; s < STAGES - 1; s++) {
        load_tile(s, s);
        cp_commit();
    }

    for (int kt = 0; kt < KT; kt++) {
        cp_wait<STAGES - 2>();
        __syncthreads();   // tile kt visible; also protects stage about to be reloaded

        const int nt = kt + STAGES - 1;
        if (nt < KT) load_tile(nt, nt % STAGES);
        cp_commit();

        const uint32_t as_u = smem_u32(smem + (long)(kt % STAGES) * STAGE_F);
        const uint32_t bs_u = as_u + BM * BK * 4;

#pragma unroll
        for (int ks = 0; ks < BK / 8; ks++) {
            uint32_t af[2][4], bf[2][4];
#pragma unroll
            for (int mi = 0; mi < 2; mi++) {
                const int row = wm + mi * 16 + arow;
                ldsm_x4(af[mi][0], af[mi][1], af[mi][2], af[mi][3],
                        as_u + (uint32_t)(row * 128 + (((ks * 2 + achk) ^ lxor) << 4)));
            }
#pragma unroll
            for (int p = 0; p < 2; p++) {
                const int row = wn + p * 16 + brow;
                // r0=b0(ni=2p) r1=b1(2p) r2=b0(2p+1) r3=b1(2p+1)
                ldsm_x4(bf[p][0], bf[p][1], bf[p][2], bf[p][3],
                        bs_u + (uint32_t)(row * 128 + (((ks * 2 + bchk) ^ lxor) << 4)));
            }
#pragma unroll
            for (int mi = 0; mi < 2; mi++)
#pragma unroll
                for (int ni = 0; ni < 4; ni++) {
                    const int p = ni >> 1, h = (ni & 1) * 2;
                    mma_tf32(c[mi][ni], af[mi][0], af[mi][1], af[mi][2], af[mi][3],
                             bf[p][h], bf[p][h + 1]);
                }
        }
    }
    cp_wait<0>();

    // -------- epilogue --------
    const long og = (long)g * o_g;
#pragma unroll
    for (int mi = 0; mi < 2; mi++) {
        const int mrow = bm * BM + wm + mi * 16 + qrow;
#pragma unroll
        for (int ni = 0; ni < 4; ni++) {
            const int ncol = bn * BN + wn + ni * 8 + qk * 2;
#pragma unroll
            for (int rr = 0; rr < 2; rr++) {
                const long mterm = og + (long)(mrow + rr * 8) * o_ldr;
#pragma unroll
                for (int cc = 0; cc < 2; cc++) {
                    const int n_g = ncol + cc;
                    const float v = c[mi][ni][rr * 2 + cc] + __ldg(bias + n_g);
                    const long oaddr = mterm + (long)(n_g >> 6) * o_ldblk + (n_g & 63);
                    if (MODE == 0) {
                        out0[oaddr] = 0.5f * v * (1.0f + erff(v * 0.70710678118654752f));
                    } else {
                        out0[oaddr] = aux0[oaddr] + 0.5f * v;
                    }
                }
            }
        }
    }
}

extern "C" void kernel_launch(void* const* d_in, const int* in_sizes, int n_in,
                              void* d_out, int out_size) {
    const float* x    = (const float*)d_in[0];
    const float* W0_1 = (const float*)d_in[1];
    const float* b0_1 = (const float*)d_in[2];
    const float* W1_1 = (const float*)d_in[3];
    const float* b1_1 = (const float*)d_in[4];
    const float* W0_2 = (const float*)d_in[5];
    const float* b0_2 = (const float*)d_in[6];
    const float* W1_2 = (const float*)d_in[7];
    const float* b1_2 = (const float*)d_in[8];
    float* out = (float*)d_out;

    void* p1 = nullptr; void* p2 = nullptr;
    cudaGetSymbolAddress(&p1, g_h1);
    cudaGetSymbolAddress(&p2, g_h2);
    float* h1 = (float*)p1;
    float* h2 = (float*)p2;

    const size_t shm = (size_t)STAGES * STAGE_F * sizeof(float);  // 73728
    cudaFuncSetAttribute(grouped_gemm<0>, cudaFuncAttributeMaxDynamicSharedMemorySize, (int)shm);
    cudaFuncSetAttribute(grouped_gemm<1>, cudaFuncAttributeMaxDynamicSharedMemorySize, (int)shm);

    dim3 blk(NTHREADS);

    // G1a: h1 = gelu(x1 @ W0_1^T + b0_1)   M=256, N=2048, K=2048, G=16
    grouped_gemm<0><<<dim3(2048 / BN, 256 / BM, 16), blk, shm>>>(
        x, 2048L, 32768L, 64L,
        W0_1, 2048L * 2048L,
        b0_1,
        h1, 2048L, 32768L, 64L,
        nullptr, 2048, 2048);

    // G2a: h2 = gelu(x2 @ W0_2^T + b0_2)   M=256, N=2048, K=1024, G=32
    // A gather: x2[b, i*64+d] = x[b,i,j,d] -> base x + j*64, ldr 32768, ldblk 2048
    grouped_gemm<0><<<dim3(2048 / BN, 256 / BM, 32), blk, shm>>>(
        x, 64L, 32768L, 2048L,
        W0_2, 2048L * 1024L,
        b0_2,
        h2, 2048L, 65536L, 64L,
        nullptr, 2048, 1024);

    // G1b: out = x + 0.5*(h1 @ W1_1^T + b1_1)   N=2048, K=2048, G=16
    grouped_gemm<1><<<dim3(2048 / BN, 256 / BM, 16), blk, shm>>>(
        h1, 2048L, 32768L, 64L,
        W1_1, 2048L * 2048L,
        b1_1,
        out, 2048L, 32768L, 64L,
        x, 2048, 2048);

    // G2b: out += 0.5*(h2 @ W1_2^T + b1_2)   N=1024, K=2048, G=32
    // out scatter: n=(i,d) -> base out + j*64, ldr 32768, ldblk 2048; aux = out (RMW)
    grouped_gemm<1><<<dim3(1024 / BN, 256 / BM, 32), blk, shm>>>(
        h2, 2048L, 65536L, 64L,
        W1_2, 1024L * 2048L,
        b1_2,
        out, 64L, 32768L, 2048L,
        out, 1024, 2048);

    (void)in_sizes; (void)n_in; (void)out_size;
}